// round 7
// baseline (speedup 1.0000x reference)
#include <cuda_runtime.h>

// Scalar damped-Newton minimization of a degree-6 polynomial (serial, 1 thread).
// Exact reference semantics:
//   g2 = inf; while (g2 > 1e-12 && it < 100):
//     g=d1(x); h=d2(x); step = h>0 ? g/h : 0.1*g; x -= step; g2 = d1(x)^2
// g carried across iterations (top-of-body g == previous g_new).
//
// Established across R1-R5: runtime is ~90% fixed structure (launch front-end,
// dependent LDG chain at idle DVFS clocks, short loop, STG/EXIT tail; bench
// dur_us adds ~2.3us graph-replay). Loop is ~40 cyc/iter critical path.
// Final micro-tweaks:
//  - exit test |g| > 1e-6 (== g^2 > 1e-12 up to square rounding; +-1 iter at
//    most, absorbed by quadratic convergence + 1e-3 tolerance). fabs is a free
//    FSETP operand modifier -> FSETP issues the cycle g is ready.
//  - x_init LDG issued first (head of the longest dependent chain).
//  - division-free select: n = x*h - g; xA = n*rcp(h); xB = x - 0.1*g;
//    x = h>0 ? xA : xB  (fallback + numerator overlap the 16-cyc MUFU shadow).

#define MAX_ITER 100
#define GRAD_TOL 1e-6f   // sqrt(1e-12)

__device__ __forceinline__ float fast_rcp(float v) {
    float r;
    asm("rcp.approx.f32 %0, %1;" : "=f"(r) : "f"(v));
    return r;
}

__global__ void __launch_bounds__(1, 1)
polymin_kernel(const float4* __restrict__ poly4,
               const float*  __restrict__ x_init,
               float* __restrict__ out) {
    // x_init first: it heads the longest dependent chain (x -> x2 -> g -> loop)
    const float  x0 = x_init[0];
    const float4 p0 = poly4[0];                   // c0..c3
    const float2 p1 = ((const float2*)poly4)[2];  // c4,c5
    const float  c6 = ((const float*)poly4)[6];

    // d1 = p' (a0..a5), d2 = p'' (b0..b4)
    const float a0 = p0.y,        a1 = p0.z * 2.0f, a2 = p0.w * 3.0f,
                a3 = p1.x * 4.0f, a4 = p1.y * 5.0f, a5 = c6  * 6.0f;
    const float b0 = a1,          b1 = a2 * 2.0f,   b2 = a3 * 3.0f,
                b3 = a4 * 4.0f,   b4 = a5 * 5.0f;

    float x  = x0;
    float x2 = x * x;
    // g = d1(x) for the first body execution (reference always enters: g2=inf)
    float g  = fmaf(fmaf(fmaf(a5, x, a4), x2, fmaf(a3, x, a2)), x2,
                    fmaf(a1, x, a0));

    #pragma unroll 1
    for (int it = 0; it < MAX_ITER; ++it) {
        // h = d2(x), Estrin off (x, x2); ready @~12
        const float h = fmaf(fmaf(b4, x2, fmaf(b3, x, b2)), x2,
                             fmaf(b1, x, b0));
        const float r  = fast_rcp(h);          // MUFU, 16-cyc shadow
        const float n  = fmaf(x, h, -g);       // Newton numerator (in shadow)
        const float xB = fmaf(-0.1f, g, x);    // GD fallback (in shadow)
        const float xA = n * r;                // Newton step result
        x  = (h > 0.0f) ? xA : xB;             // FSEL, pred-as-data
        x2 = x * x;
        // g_new = d1(x_new); exit compare issues the cycle g is ready
        g  = fmaf(fmaf(fmaf(a5, x, a4), x2, fmaf(a3, x, a2)), x2,
                  fmaf(a1, x, a0));
        if (!(fabsf(g) > GRAD_TOL)) break;
    }

    out[0] = x;
}

extern "C" void kernel_launch(void* const* d_in, const int* in_sizes, int n_in,
                              void* d_out, int out_size) {
    const float4* poly   = (const float4*)d_in[0];  // 7 fp32
    const float*  x_init = (const float*)d_in[1];   // 1 fp32
    polymin_kernel<<<1, 1>>>(poly, x_init, (float*)d_out);
}